// round 2
// baseline (speedup 1.0000x reference)
#include <cuda_runtime.h>
#include <math.h>

// Problem constants
#define TLEN   2048
#define FDIM   256
#define NHEAD  8
#define NBATCH 4
#define NBH    32   // NBATCH * NHEAD

// GEMM tiling
constexpr int BM = 128, BN = 128, BK = 16;

// Scratch (allocation-free rule: __device__ globals)
__device__ float g_Q   [(size_t)NBH * TLEN * FDIM];            // 64 MB
__device__ float g_Kb  [(size_t)NBH * TLEN * FDIM];            // 64 MB
__device__ float g_V   [(size_t)NBH * TLEN * FDIM];            // 64 MB
__device__ float g_S   [(size_t)NBH * TLEN * TLEN];            // 512 MB
__device__ float g_attn[(size_t)NBATCH * TLEN * NHEAD * FDIM]; // 64 MB

// MODE 0: QKV   C[8192,6144] = x @ W_qkv + b, scatter -> Q/K/V [B,H,T,F], scale Q,K by 1/16
// MODE 1: SCORE C[2048,2048] = Q_bh @ K_bh^T (NT), z = b*H+h, store to g_S
// MODE 2: PV    C[2048, 256] = S_bh @ V_bh (NN), store to g_attn [B,T,H*F]
// MODE 3: PROJ  C[8192, 256] = attn @ W_proj + b_proj -> d_out
template<int MODE>
__global__ void __launch_bounds__(256)
gemm_kernel(const float* __restrict__ Agp, const float* __restrict__ Bgp,
            const float* __restrict__ bias, float* __restrict__ Cgp,
            int M, int N, int K)
{
    __shared__ float As[BK][BM + 4];
    __shared__ float Bs[BK][BN + 4];

    const int tid = threadIdx.x;
    const int tx = tid & 15, ty = tid >> 4;
    const int z  = blockIdx.z;
    const int rowBase = blockIdx.y * BM;
    const int colBase = blockIdx.x * BN;

    const float* __restrict__ A;
    const float* __restrict__ B;
    if      (MODE == 0) { A = Agp;                              B = Bgp; }
    else if (MODE == 1) { A = g_Q  + (size_t)z * TLEN * FDIM;   B = g_Kb + (size_t)z * TLEN * FDIM; }
    else if (MODE == 2) { A = g_S  + (size_t)z * TLEN * TLEN;   B = g_V  + (size_t)z * TLEN * FDIM; }
    else                { A = g_attn;                           B = Bgp; }

    constexpr bool TRANSB = (MODE == 1);

    // A tile: BM x BK (128x16) = 512 float4; each thread loads 2
    const int ar0 = tid >> 2;          // 0..63
    const int ar1 = (tid + 256) >> 2;  // 64..127
    const int akc = (tid & 3) << 2;    // 0,4,8,12
    // B tile NN: BK x BN (16x128)
    const int bnr0 = tid >> 5;            // 0..7
    const int bnr1 = (tid + 256) >> 5;    // 8..15
    const int bnc  = (tid & 31) << 2;     // 0..124

    const float* Arow = A + (size_t)rowBase * K;

    float4 a0, a1, b0, b1;

    // --- prologue: load tile kt=0 ---
    {
        a0 = *(const float4*)(Arow + (size_t)ar0 * K + akc);
        a1 = *(const float4*)(Arow + (size_t)ar1 * K + akc);
        if (TRANSB) {
            const float* Bp = B + (size_t)colBase * K;
            b0 = *(const float4*)(Bp + (size_t)ar0 * K + akc);
            b1 = *(const float4*)(Bp + (size_t)ar1 * K + akc);
        } else {
            const float* Bp = B + colBase;
            b0 = *(const float4*)(Bp + (size_t)bnr0 * N + bnc);
            b1 = *(const float4*)(Bp + (size_t)bnr1 * N + bnc);
        }
    }
    // store to smem
    {
        As[akc + 0][ar0] = a0.x; As[akc + 1][ar0] = a0.y; As[akc + 2][ar0] = a0.z; As[akc + 3][ar0] = a0.w;
        As[akc + 0][ar1] = a1.x; As[akc + 1][ar1] = a1.y; As[akc + 2][ar1] = a1.z; As[akc + 3][ar1] = a1.w;
        if (TRANSB) {
            Bs[akc + 0][ar0] = b0.x; Bs[akc + 1][ar0] = b0.y; Bs[akc + 2][ar0] = b0.z; Bs[akc + 3][ar0] = b0.w;
            Bs[akc + 0][ar1] = b1.x; Bs[akc + 1][ar1] = b1.y; Bs[akc + 2][ar1] = b1.z; Bs[akc + 3][ar1] = b1.w;
        } else {
            *(float4*)&Bs[bnr0][bnc] = b0;
            *(float4*)&Bs[bnr1][bnc] = b1;
        }
    }
    __syncthreads();

    float acc[8][8] = {};
    const int KT = K / BK;

    for (int kt = 0; kt < KT; ++kt) {
        // prefetch next tile global -> regs
        if (kt + 1 < KT) {
            const int k0 = (kt + 1) * BK;
            a0 = *(const float4*)(Arow + (size_t)ar0 * K + k0 + akc);
            a1 = *(const float4*)(Arow + (size_t)ar1 * K + k0 + akc);
            if (TRANSB) {
                const float* Bp = B + (size_t)colBase * K + k0;
                b0 = *(const float4*)(Bp + (size_t)ar0 * K + akc);
                b1 = *(const float4*)(Bp + (size_t)ar1 * K + akc);
            } else {
                const float* Bp = B + colBase + (size_t)k0 * N;
                b0 = *(const float4*)(Bp + (size_t)bnr0 * N + bnc);
                b1 = *(const float4*)(Bp + (size_t)bnr1 * N + bnc);
            }
        }

        #pragma unroll
        for (int k = 0; k < BK; ++k) {
            float4 x0 = *(const float4*)&As[k][ty * 8];
            float4 x1 = *(const float4*)&As[k][ty * 8 + 4];
            float4 y0 = *(const float4*)&Bs[k][tx * 8];
            float4 y1 = *(const float4*)&Bs[k][tx * 8 + 4];
            float ra[8] = {x0.x, x0.y, x0.z, x0.w, x1.x, x1.y, x1.z, x1.w};
            float rb[8] = {y0.x, y0.y, y0.z, y0.w, y1.x, y1.y, y1.z, y1.w};
            #pragma unroll
            for (int i = 0; i < 8; ++i)
                #pragma unroll
                for (int j = 0; j < 8; ++j)
                    acc[i][j] = fmaf(ra[i], rb[j], acc[i][j]);
        }
        __syncthreads();

        if (kt + 1 < KT) {
            As[akc + 0][ar0] = a0.x; As[akc + 1][ar0] = a0.y; As[akc + 2][ar0] = a0.z; As[akc + 3][ar0] = a0.w;
            As[akc + 0][ar1] = a1.x; As[akc + 1][ar1] = a1.y; As[akc + 2][ar1] = a1.z; As[akc + 3][ar1] = a1.w;
            if (TRANSB) {
                Bs[akc + 0][ar0] = b0.x; Bs[akc + 1][ar0] = b0.y; Bs[akc + 2][ar0] = b0.z; Bs[akc + 3][ar0] = b0.w;
                Bs[akc + 0][ar1] = b1.x; Bs[akc + 1][ar1] = b1.y; Bs[akc + 2][ar1] = b1.z; Bs[akc + 3][ar1] = b1.w;
            } else {
                *(float4*)&Bs[bnr0][bnc] = b0;
                *(float4*)&Bs[bnr1][bnc] = b1;
            }
            __syncthreads();
        }
    }

    // --- epilogue ---
    const int r0 = rowBase + ty * 8;
    const int c0 = colBase + tx * 8;

    if (MODE == 0) {
        #pragma unroll
        for (int i = 0; i < 8; ++i) {
            const int bt = r0 + i;
            const int b = bt >> 11;       // / TLEN
            const int t = bt & (TLEN - 1);
            #pragma unroll
            for (int j = 0; j < 8; ++j) {
                const int jj = c0 + j;
                float v = acc[i][j] + bias[jj];
                const int h = jj / (FDIM * 3);
                const int r = jj - h * (FDIM * 3);
                const int f = r / 3;
                const int c = r - f * 3;
                const size_t idx = (((size_t)(b * NHEAD + h)) * TLEN + t) * FDIM + f;
                if      (c == 0) g_Q [idx] = v * 0.0625f;  // 1/sqrt(256)
                else if (c == 1) g_Kb[idx] = v * 0.0625f;
                else             g_V [idx] = v;
            }
        }
    } else if (MODE == 1) {
        float* C = g_S + (size_t)z * TLEN * TLEN;
        #pragma unroll
        for (int i = 0; i < 8; ++i) {
            float* p = C + (size_t)(r0 + i) * TLEN + c0;
            *(float4*)(p)     = make_float4(acc[i][0], acc[i][1], acc[i][2], acc[i][3]);
            *(float4*)(p + 4) = make_float4(acc[i][4], acc[i][5], acc[i][6], acc[i][7]);
        }
    } else if (MODE == 2) {
        const int b = z >> 3, h = z & 7;
        #pragma unroll
        for (int i = 0; i < 8; ++i) {
            float* p = g_attn + ((size_t)(b * TLEN + r0 + i)) * (NHEAD * FDIM) + h * FDIM + c0;
            *(float4*)(p)     = make_float4(acc[i][0], acc[i][1], acc[i][2], acc[i][3]);
            *(float4*)(p + 4) = make_float4(acc[i][4], acc[i][5], acc[i][6], acc[i][7]);
        }
    } else {
        const float4 bv0 = *(const float4*)(bias + c0);
        const float4 bv1 = *(const float4*)(bias + c0 + 4);
        #pragma unroll
        for (int i = 0; i < 8; ++i) {
            float* p = Cgp + (size_t)(r0 + i) * N + c0;
            *(float4*)(p)     = make_float4(acc[i][0] + bv0.x, acc[i][1] + bv0.y,
                                            acc[i][2] + bv0.z, acc[i][3] + bv0.w);
            *(float4*)(p + 4) = make_float4(acc[i][4] + bv1.x, acc[i][5] + bv1.y,
                                            acc[i][6] + bv1.z, acc[i][7] + bv1.w);
        }
    }
}

// Row softmax over g_S: 65536 rows of 2048
__global__ void __launch_bounds__(256) softmax_kernel()
{
    const size_t row = blockIdx.x;
    float* p = g_S + row * (size_t)TLEN;
    const int t = threadIdx.x;

    float4 v0 = ((float4*)p)[t];
    float4 v1 = ((float4*)p)[t + 256];

    float m = fmaxf(fmaxf(fmaxf(v0.x, v0.y), fmaxf(v0.z, v0.w)),
                    fmaxf(fmaxf(v1.x, v1.y), fmaxf(v1.z, v1.w)));
    #pragma unroll
    for (int o = 16; o; o >>= 1) m = fmaxf(m, __shfl_xor_sync(0xffffffffu, m, o));

    __shared__ float red[8];
    const int warp = t >> 5, lane = t & 31;
    if (lane == 0) red[warp] = m;
    __syncthreads();
    float bm = red[0];
    #pragma unroll
    for (int i = 1; i < 8; ++i) bm = fmaxf(bm, red[i]);
    __syncthreads();

    v0.x = __expf(v0.x - bm); v0.y = __expf(v0.y - bm);
    v0.z = __expf(v0.z - bm); v0.w = __expf(v0.w - bm);
    v1.x = __expf(v1.x - bm); v1.y = __expf(v1.y - bm);
    v1.z = __expf(v1.z - bm); v1.w = __expf(v1.w - bm);

    float s = v0.x + v0.y + v0.z + v0.w + v1.x + v1.y + v1.z + v1.w;
    #pragma unroll
    for (int o = 16; o; o >>= 1) s += __shfl_xor_sync(0xffffffffu, s, o);
    if (lane == 0) red[warp] = s;
    __syncthreads();
    float bs = 0.f;
    #pragma unroll
    for (int i = 0; i < 8; ++i) bs += red[i];

    const float inv = 1.0f / bs;
    v0.x *= inv; v0.y *= inv; v0.z *= inv; v0.w *= inv;
    v1.x *= inv; v1.y *= inv; v1.z *= inv; v1.w *= inv;

    ((float4*)p)[t]       = v0;
    ((float4*)p)[t + 256] = v1;
}

extern "C" void kernel_launch(void* const* d_in, const int* in_sizes, int n_in,
                              void* d_out, int out_size)
{
    const float* x     = (const float*)d_in[0];
    const float* Wqkv  = (const float*)d_in[1];
    const float* bqkv  = (const float*)d_in[2];
    const float* Wproj = (const float*)d_in[3];
    const float* bproj = (const float*)d_in[4];
    float* out = (float*)d_out;

    const int Mx = NBATCH * TLEN;          // 8192
    const int Nqkv = NHEAD * FDIM * 3;     // 6144

    // 1) QKV GEMM + scatter
    gemm_kernel<0><<<dim3(Nqkv / BN, Mx / BM, 1), 256>>>(x, Wqkv, bqkv, nullptr,
                                                         Mx, Nqkv, FDIM);
    // 2) scores = Q K^T (batched over 32 bh)
    gemm_kernel<1><<<dim3(TLEN / BN, TLEN / BM, NBH), 256>>>(nullptr, nullptr, nullptr, nullptr,
                                                             TLEN, TLEN, FDIM);
    // 3) softmax rows
    softmax_kernel<<<NBH * TLEN, 256>>>();
    // 4) out_bh = P V  (batched), scatter into [B,T,H*F]
    gemm_kernel<2><<<dim3(FDIM / BN, TLEN / BM, NBH), 256>>>(nullptr, nullptr, nullptr, nullptr,
                                                             TLEN, FDIM, TLEN);
    // 5) proj
    gemm_kernel<3><<<dim3(FDIM / BN, Mx / BM, 1), 256>>>(nullptr, Wproj, bproj, out,
                                                         Mx, FDIM, TLEN);
}